// round 1
// baseline (speedup 1.0000x reference)
#include <cuda_runtime.h>

// GCMConv: gauge-covariant convolution on 8x8x16x16 lattice.
// x: (1, 16384, 8, 3, 3, 2) float32  [channels: 4 gauge links U_a, 4 fields w_c]
// weight: (4, 9, 33) float32
// out: (1, 16384, 8, 3, 3, 2): [U (copied), w_out]

#define NS 16384
#define IDX(i,j,r) ((i)*6 + (j)*2 + (r))

// Scratch: element-major [(k*18 + e)*NS + site].
// k = 0..15 : transported matrices T_{a*4+c} = U_a(x) w_c(x+a) U_a(x)^dag
// k = 16..19: own-site fields w_c (transposed copy for coalesced reads)
__device__ float g_T[20 * 18 * NS];

__device__ __forceinline__ void cmul(const float (&A)[18], const float (&B)[18],
                                     float (&C)[18]) {
    // C = A @ B (complex 3x3)
#pragma unroll
    for (int i = 0; i < 3; i++)
#pragma unroll
        for (int k = 0; k < 3; k++) {
            float cr = 0.f, ci = 0.f;
#pragma unroll
            for (int j = 0; j < 3; j++) {
                float ar = A[IDX(i, j, 0)], ai = A[IDX(i, j, 1)];
                float br = B[IDX(j, k, 0)], bi = B[IDX(j, k, 1)];
                cr += ar * br - ai * bi;
                ci += ar * bi + ai * br;
            }
            C[IDX(i, k, 0)] = cr;
            C[IDX(i, k, 1)] = ci;
        }
}

__device__ __forceinline__ void cmul_dagB(const float (&A)[18], const float (&B)[18],
                                          float (&C)[18]) {
    // C = A @ B^dagger : C[i,k] = sum_j A[i,j] * conj(B[k,j])
#pragma unroll
    for (int i = 0; i < 3; i++)
#pragma unroll
        for (int k = 0; k < 3; k++) {
            float cr = 0.f, ci = 0.f;
#pragma unroll
            for (int j = 0; j < 3; j++) {
                float ar = A[IDX(i, j, 0)], ai = A[IDX(i, j, 1)];
                float br = B[IDX(k, j, 0)], bi = -B[IDX(k, j, 1)];
                cr += ar * br - ai * bi;
                ci += ar * bi + ai * br;
            }
            C[IDX(i, k, 0)] = cr;
            C[IDX(i, k, 1)] = ci;
        }
}

__global__ __launch_bounds__(256) void transport_kernel(const float* __restrict__ x) {
    int g = blockIdx.x * blockDim.x + threadIdx.x;
    int site = g & (NS - 1);
    int k = g >> 14;

    if (k >= 16) {
        // copy own-site field w_c into element-major scratch
        int c = k - 16;
        const float* wp = x + site * 144 + (4 + c) * 18;
#pragma unroll
        for (int e = 0; e < 18; e++)
            g_T[(k * 18 + e) * NS + site] = wp[e];
        return;
    }

    int a = k >> 2, c = k & 3;

    // periodic neighbor site in +axis direction; dims (8,8,16,16), strides (2048,256,16,1)
    int d3 = site & 15;
    int d2 = (site >> 4) & 15;
    int d1 = (site >> 8) & 7;
    int d0 = (site >> 11) & 7;
    int nbr;
    if (a == 0)      nbr = site + ((((d0 + 1) & 7) - d0) << 11);
    else if (a == 1) nbr = site + ((((d1 + 1) & 7) - d1) << 8);
    else if (a == 2) nbr = site + ((((d2 + 1) & 15) - d2) << 4);
    else             nbr = site + (((d3 + 1) & 15) - d3);

    float U[18], Wn[18], t1[18], T[18];
    const float* up = x + site * 144 + a * 18;
    const float* wp = x + nbr * 144 + (4 + c) * 18;
#pragma unroll
    for (int e = 0; e < 18; e++) { U[e] = up[e]; Wn[e] = wp[e]; }

    cmul(U, Wn, t1);       // t1 = U @ w(x+a)
    cmul_dagB(t1, U, T);   // T  = t1 @ U^dag

#pragma unroll
    for (int e = 0; e < 18; e++)
        g_T[(k * 18 + e) * NS + site] = T[e];
}

__global__ __launch_bounds__(128) void contract_kernel(const float* __restrict__ x,
                                                       const float* __restrict__ weight,
                                                       float* __restrict__ out) {
    __shared__ float wu[297];  // weight slice for this block's output channel u

    int g = blockIdx.x * 128 + threadIdx.x;
    int site = g & (NS - 1);
    int u = g >> 14;  // entire block shares one u (NS % 128 == 0)

    for (int e = threadIdx.x; e < 297; e += 128)
        wu[e] = weight[u * 297 + e];
    __syncthreads();

    // copy gauge link channel u to output
    {
        const float* src = x + site * 144 + u * 18;
        float* dst = out + site * 144 + u * 18;
#pragma unroll
        for (int e = 0; e < 18; e++) dst[e] = src[e];
    }

    // M[v] = sum_w weight[u,v,w] * B_w, with B = {T_k (k<16), T_k^dag, I}
    float M[9][18];
#pragma unroll
    for (int v = 0; v < 9; v++) {
        float cI = wu[v * 33 + 32];
#pragma unroll
        for (int e = 0; e < 18; e++) M[v][e] = 0.f;
        M[v][IDX(0, 0, 0)] = cI;
        M[v][IDX(1, 1, 0)] = cI;
        M[v][IDX(2, 2, 0)] = cI;
    }

#pragma unroll 2
    for (int k = 0; k < 16; k++) {
        float T[18];
#pragma unroll
        for (int e = 0; e < 18; e++)
            T[e] = g_T[(k * 18 + e) * NS + site];
#pragma unroll
        for (int v = 0; v < 9; v++) {
            float c1 = wu[v * 33 + k];        // coeff of T_k
            float c2 = wu[v * 33 + 16 + k];   // coeff of T_k^dag
#pragma unroll
            for (int i = 0; i < 3; i++)
#pragma unroll
                for (int j = 0; j < 3; j++) {
                    M[v][IDX(i, j, 0)] += c1 * T[IDX(i, j, 0)] + c2 * T[IDX(j, i, 0)];
                    M[v][IDX(i, j, 1)] += c1 * T[IDX(i, j, 1)] - c2 * T[IDX(j, i, 1)];
                }
        }
    }

    // acc = sum_v A_v @ M[v], A = {w_c (v<4), w_c^dag (v=4..7), I (v=8)}
    float acc[18];
#pragma unroll
    for (int e = 0; e < 18; e++) acc[e] = M[8][e];

#pragma unroll
    for (int c = 0; c < 4; c++) {
        float wc[18];
#pragma unroll
        for (int e = 0; e < 18; e++)
            wc[e] = g_T[((16 + c) * 18 + e) * NS + site];
#pragma unroll
        for (int i = 0; i < 3; i++)
#pragma unroll
            for (int kk = 0; kk < 3; kk++) {
                float cr = acc[IDX(i, kk, 0)], ci = acc[IDX(i, kk, 1)];
#pragma unroll
                for (int j = 0; j < 3; j++) {
                    // acc += wc @ M[c]
                    float ar = wc[IDX(i, j, 0)], ai = wc[IDX(i, j, 1)];
                    float br = M[c][IDX(j, kk, 0)], bi = M[c][IDX(j, kk, 1)];
                    cr += ar * br - ai * bi;
                    ci += ar * bi + ai * br;
                    // acc += wc^dag @ M[4+c] : (wc^dag)[i,j] = conj(wc[j,i])
                    float dr = wc[IDX(j, i, 0)], di = -wc[IDX(j, i, 1)];
                    float er = M[4 + c][IDX(j, kk, 0)], ei = M[4 + c][IDX(j, kk, 1)];
                    cr += dr * er - di * ei;
                    ci += dr * ei + di * er;
                }
                acc[IDX(i, kk, 0)] = cr;
                acc[IDX(i, kk, 1)] = ci;
            }
    }

    float* dst = out + site * 144 + (4 + u) * 18;
#pragma unroll
    for (int e = 0; e < 18; e++) dst[e] = acc[e];
}

extern "C" void kernel_launch(void* const* d_in, const int* in_sizes, int n_in,
                              void* d_out, int out_size) {
    const float* x = (const float*)d_in[0];
    const float* weight = (const float*)d_in[1];
    float* out = (float*)d_out;

    transport_kernel<<<20 * NS / 256, 256>>>(x);
    contract_kernel<<<4 * NS / 128, 128>>>(x, weight, out);
}

// round 2
// speedup vs baseline: 1.3040x; 1.3040x over previous
#include <cuda_runtime.h>

// GCMConv: gauge-covariant convolution on 8x8x16x16 lattice.
// x: (1, 16384, 8, 3, 3, 2) float32  [channels: 4 gauge links U_a, 4 fields w_c]
// weight: (4, 9, 33) float32
// out: (1, 16384, 8, 3, 3, 2): [U (copied), w_out]
//
// Factorization: w_out[u] = sum_w (sum_v weight[u,v,w] A_v) B_w
//                        = init(A, c_32) + sum_k P1_k @ T_k + P2_k @ T_k^dag
// where A = {w_c, w_c^dag, I} (site-resident), B = {T_k, T_k^dag, I}.

#define NS 16384

// Scratch: [(k*9 + m)*NS + site] float2 (re,im), m = row*3+col.
// k = 0..15 : T_{a*4+c} = U_a(x) w_c(x+a) U_a(x)^dag
// k = 16..19: own-site fields w_c
__device__ float2 g_T[20 * 9 * NS];

__global__ __launch_bounds__(256) void transport_kernel(const float* __restrict__ x) {
    int g = blockIdx.x * 256 + threadIdx.x;   // 0 .. 4*NS-1
    int site = g & (NS - 1);
    int a = g >> 14;                           // axis 0..3

    // periodic +1 neighbor; dims (8,8,16,16), strides (2048,256,16,1)
    int d3 = site & 15, d2 = (site >> 4) & 15, d1 = (site >> 8) & 7, d0 = (site >> 11) & 7;
    int nbr;
    if (a == 0)      nbr = site + ((((d0 + 1) & 7) - d0) << 11);
    else if (a == 1) nbr = site + ((((d1 + 1) & 7) - d1) << 8);
    else if (a == 2) nbr = site + ((((d2 + 1) & 15) - d2) << 4);
    else             nbr = site + (((d3 + 1) & 15) - d3);

    float Ur[3][3], Ui[3][3];
    {
        const float2* up = (const float2*)(x + site * 144 + a * 18);
#pragma unroll
        for (int m = 0; m < 9; m++) {
            float2 t = up[m];
            Ur[m / 3][m % 3] = t.x;
            Ui[m / 3][m % 3] = t.y;
        }
    }

#pragma unroll
    for (int c = 0; c < 4; c++) {
        float Wr[3][3], Wi[3][3];
        const float2* wp = (const float2*)(x + nbr * 144 + (4 + c) * 18);
#pragma unroll
        for (int m = 0; m < 9; m++) {
            float2 t = wp[m];
            Wr[m / 3][m % 3] = t.x;
            Wi[m / 3][m % 3] = t.y;
        }
        // t1 = U @ W
        float t1r[3][3], t1i[3][3];
#pragma unroll
        for (int i = 0; i < 3; i++)
#pragma unroll
            for (int kk = 0; kk < 3; kk++) {
                float cr = 0.f, ci = 0.f;
#pragma unroll
                for (int j = 0; j < 3; j++) {
                    cr += Ur[i][j] * Wr[j][kk] - Ui[i][j] * Wi[j][kk];
                    ci += Ur[i][j] * Wi[j][kk] + Ui[i][j] * Wr[j][kk];
                }
                t1r[i][kk] = cr;
                t1i[i][kk] = ci;
            }
        // T = t1 @ U^dag : T[i][k] = sum_j t1[i][j] * conj(U[k][j])
        int kbase = (a * 4 + c) * 9;
#pragma unroll
        for (int i = 0; i < 3; i++)
#pragma unroll
            for (int kk = 0; kk < 3; kk++) {
                float cr = 0.f, ci = 0.f;
#pragma unroll
                for (int j = 0; j < 3; j++) {
                    float br = Ur[kk][j], bi = -Ui[kk][j];
                    cr += t1r[i][j] * br - t1i[i][j] * bi;
                    ci += t1r[i][j] * bi + t1i[i][j] * br;
                }
                g_T[(kbase + i * 3 + kk) * NS + site] = make_float2(cr, ci);
            }
    }

    // fold own-site field copy: thread (site, a) copies channel c = a
    {
        const float2* wp = (const float2*)(x + site * 144 + (4 + a) * 18);
        int kbase = (16 + a) * 9;
#pragma unroll
        for (int m = 0; m < 9; m++)
            g_T[(kbase + m) * NS + site] = wp[m];
    }
}

__global__ __launch_bounds__(128, 3) void contract_kernel(const float* __restrict__ x,
                                                          const float* __restrict__ weight,
                                                          float* __restrict__ out) {
    __shared__ float wt[297];  // transposed weight slice: wt[w*9 + v] = weight[u, v, w]

    int g = blockIdx.x * 128 + threadIdx.x;
    int site = g & (NS - 1);
    int u = g >> 14;  // whole block shares one u

    for (int s = threadIdx.x; s < 297; s += 128) {
        int v = s / 33, w = s % 33;
        wt[w * 9 + v] = weight[u * 297 + s];
    }
    __syncthreads();

    // copy gauge link channel u to output
    {
        const float2* src = (const float2*)(x + site * 144 + u * 18);
        float2* dst = (float2*)(out + site * 144 + u * 18);
#pragma unroll
        for (int m = 0; m < 9; m++) dst[m] = src[m];
    }

    // load own-site fields
    float wcr[4][3][3], wci[4][3][3];
#pragma unroll
    for (int c = 0; c < 4; c++)
#pragma unroll
        for (int m = 0; m < 9; m++) {
            float2 t = g_T[((16 + c) * 9 + m) * NS + site];
            wcr[c][m / 3][m % 3] = t.x;
            wci[c][m / 3][m % 3] = t.y;
        }

    // init: acc = sum_v wt[32*9+v] * A_v   (B_32 = I)
    float ar[3][3], ai[3][3];
    {
        const float* cc = &wt[32 * 9];
#pragma unroll
        for (int i = 0; i < 3; i++)
#pragma unroll
            for (int j = 0; j < 3; j++) {
                float r = (i == j) ? cc[8] : 0.f, im = 0.f;
#pragma unroll
                for (int c = 0; c < 4; c++) {
                    r  += cc[c] * wcr[c][i][j] + cc[4 + c] * wcr[c][j][i];
                    im += cc[c] * wci[c][i][j] - cc[4 + c] * wci[c][j][i];
                }
                ar[i][j] = r;
                ai[i][j] = im;
            }
    }

    // k-loop: acc += P1_k @ T_k + P2_k @ T_k^dag, P built row-fused (4-float transient)
    float2 Tb[2][9];
#pragma unroll
    for (int m = 0; m < 9; m++) Tb[0][m] = g_T[m * NS + site];

#pragma unroll 2
    for (int k = 0; k < 16; k++) {
        int cur = k & 1;
        if (k < 15) {
#pragma unroll
            for (int m = 0; m < 9; m++)
                Tb[cur ^ 1][m] = g_T[((k + 1) * 9 + m) * NS + site];
        }
        const float* c1 = &wt[k * 9];
        const float* c2 = &wt[(16 + k) * 9];
#pragma unroll
        for (int i = 0; i < 3; i++)
#pragma unroll
            for (int j = 0; j < 3; j++) {
                float p1r = (i == j) ? c1[8] : 0.f, p1i = 0.f;
                float p2r = (i == j) ? c2[8] : 0.f, p2i = 0.f;
#pragma unroll
                for (int c = 0; c < 4; c++) {
                    p1r += c1[c] * wcr[c][i][j] + c1[4 + c] * wcr[c][j][i];
                    p1i += c1[c] * wci[c][i][j] - c1[4 + c] * wci[c][j][i];
                    p2r += c2[c] * wcr[c][i][j] + c2[4 + c] * wcr[c][j][i];
                    p2i += c2[c] * wci[c][i][j] - c2[4 + c] * wci[c][j][i];
                }
#pragma unroll
                for (int l = 0; l < 3; l++) {
                    float tr = Tb[cur][j * 3 + l].x, ti = Tb[cur][j * 3 + l].y;
                    float sr = Tb[cur][l * 3 + j].x, si = Tb[cur][l * 3 + j].y;
                    // P1 * T[j][l]  +  P2 * conj(T[l][j])
                    ar[i][l] += p1r * tr - p1i * ti + p2r * sr + p2i * si;
                    ai[i][l] += p1r * ti + p1i * tr - p2r * si + p2i * sr;
                }
            }
    }

    float2* dst = (float2*)(out + site * 144 + (4 + u) * 18);
#pragma unroll
    for (int i = 0; i < 3; i++)
#pragma unroll
        for (int j = 0; j < 3; j++)
            dst[i * 3 + j] = make_float2(ar[i][j], ai[i][j]);
}

extern "C" void kernel_launch(void* const* d_in, const int* in_sizes, int n_in,
                              void* d_out, int out_size) {
    const float* x = (const float*)d_in[0];
    const float* weight = (const float*)d_in[1];
    float* out = (float*)d_out;

    transport_kernel<<<4 * NS / 256, 256>>>(x);
    contract_kernel<<<4 * NS / 128, 128>>>(x, weight, out);
}